// round 15
// baseline (speedup 1.0000x reference)
#include <cuda_runtime.h>
#include <cuda_fp16.h>
#include <cstdint>

#define M_TOK 64
#define N_OUT 8192
#define K_IN  8192
#define NG    64            // K groups per row (8192/128)
#define NTILES (N_OUT / 64) // 128
#define WTOTAL (NTILES * NG)// 8192 work units
#define NCTA  296           // 2 per SM on 148 SMs
#define BN    64
#define BK    128
#define LDK   136
#define NTHREADS 256
#define ABYTES (M_TOK * LDK * 2)
#define BBYTES (BN * LDK * 2)
#define SMEM_BYTES (2 * ABYTES + 2 * BBYTES)  // 69632 B -> 2 CTA/SM

__device__ float g_part[NCTA * 2 * 4096];    // stream-K partials
__device__ int   g_cnt[NTILES];              // per-ntile arrival counters (self-resetting)

__device__ __forceinline__ int gsplit(int c) { return (int)(((long long)c * WTOTAL) / NCTA); }

__device__ __forceinline__ void ldsm4(uint32_t& r0, uint32_t& r1, uint32_t& r2, uint32_t& r3,
                                      uint32_t a) {
    asm volatile("ldmatrix.sync.aligned.m8n8.x4.shared.b16 {%0,%1,%2,%3}, [%4];"
                 : "=r"(r0), "=r"(r1), "=r"(r2), "=r"(r3) : "r"(a));
}
__device__ __forceinline__ void mma_16816(float c[4],
                                          uint32_t a0, uint32_t a1, uint32_t a2, uint32_t a3,
                                          uint32_t b0, uint32_t b1) {
    asm volatile("mma.sync.aligned.m16n8k16.row.col.f32.f16.f16.f32 "
                 "{%0,%1,%2,%3}, {%4,%5,%6,%7}, {%8,%9}, {%0,%1,%2,%3};"
                 : "+f"(c[0]), "+f"(c[1]), "+f"(c[2]), "+f"(c[3])
                 : "r"(a0), "r"(a1), "r"(a2), "r"(a3), "r"(b0), "r"(b1));
}

__global__ void __launch_bounds__(NTHREADS, 2)
woq_gemm_kernel(const float* __restrict__ x,
                const int* __restrict__ qw,
                const float* __restrict__ sz,
                float* __restrict__ out)
{
    extern __shared__ __half smem[];
    __half* Bs = smem + 2 * M_TOK * LDK;

    const int tid  = threadIdx.x;
    const int lane = tid & 31;
    const int warp = tid >> 5;
    const int wm   = warp & 3;
    const int wn   = warp >> 2;
    const int cta  = blockIdx.x;

    const int w0 = gsplit(cta);
    const int w1 = gsplit(cta + 1);

    float acc[4][4];
    #pragma unroll
    for (int i = 0; i < 4; ++i)
        #pragma unroll
        for (int j = 0; j < 4; ++j) acc[i][j] = 0.f;

    const uint32_t s_base = (uint32_t)__cvta_generic_to_shared(smem);
    const uint32_t as_b = s_base;
    const uint32_t bs_b = s_base + 2 * ABYTES;

    const uint32_t a_off  = as_b + 2u * ((wm * 16 + (lane & 15)) * LDK + (lane >> 4) * 8);
    const uint32_t b_off0 = bs_b + 2u * ((wn * 32 + (lane & 7) + ((lane >> 4) << 3)) * LDK
                                         + ((lane >> 3) & 1) * 8);
    const uint32_t b_off1 = b_off0 + 2u * 16 * LDK;

    // x staging: thread covers rows (j*16 + tid>>4), 8 fp32 at cols (tid&15)*8
    const int xrow0 = tid >> 4;
    const int xcol  = tid & 15;
    const float* xsrc = x + (size_t)xrow0 * K_IN + xcol * 8;
    __half* adst = smem + xrow0 * LDK + xcol * 8;

    // stage the x tile for group g into As buffer pbuf (fp32 -> fp16 in regs)
    auto stage_x = [&](int g, int pbuf) {
        const int k0 = g * BK;
        __half* ad = adst + pbuf * (M_TOK * LDK);
        #pragma unroll
        for (int j = 0; j < 4; ++j) {
            const float* s = xsrc + (size_t)j * 16 * K_IN + k0;
            float4 a = *reinterpret_cast<const float4*>(s);
            float4 b = *reinterpret_cast<const float4*>(s + 4);
            __half2 h0 = __floats2half2_rn(a.x, a.y);
            __half2 h1 = __floats2half2_rn(a.z, a.w);
            __half2 h2 = __floats2half2_rn(b.x, b.y);
            __half2 h3 = __floats2half2_rn(b.z, b.w);
            uint4 pk;
            pk.x = *reinterpret_cast<uint32_t*>(&h0);
            pk.y = *reinterpret_cast<uint32_t*>(&h1);
            pk.z = *reinterpret_cast<uint32_t*>(&h2);
            pk.w = *reinterpret_cast<uint32_t*>(&h3);
            *reinterpret_cast<uint4*>(ad + j * 16 * LDK) = pk;
        }
    };

    int4     wq[8];    // staged weights for CURRENT chunk
    uint32_t szr[8];   // packed (s,z) half2 for CURRENT chunk

    const int*    qbase  = qw + (size_t)warp * K_IN + lane * 4;
    const float2* szbase = reinterpret_cast<const float2*>(sz) + warp;

    // ---- prologue: regs for chunk w0 + stage As[0] ----
    {
        const int g  = w0 & (NG - 1);
        const int nb = (w0 >> 6) << 6;
        const int* qr = qbase + (size_t)nb * K_IN + g * BK;
        #pragma unroll
        for (int it = 0; it < 8; ++it)
            wq[it] = *reinterpret_cast<const int4*>(qr + (size_t)(it * 8) * K_IN);
        const float2* szp = szbase + (size_t)g * N_OUT + nb;
        #pragma unroll
        for (int it = 0; it < 8; ++it) {
            float2 v = szp[it * 8];
            __half2 h = __floats2half2_rn(v.x, v.y);
            szr[it] = *reinterpret_cast<uint32_t*>(&h);
        }
        stage_x(g, 0);
    }

    const __half2 k1032 = __floats2half2_rn(1032.f, 1032.f);
    int seg = 0;

    for (int w = w0; w < w1; ++w) {
        const int p = (w - w0) & 1;

        const int wn_ = (w + 1 < w1) ? (w + 1) : w;
        const int gN  = wn_ & (NG - 1);
        const int nbN = (wn_ >> 6) << 6;
        const int* qrN = qbase + (size_t)nbN * K_IN + gN * BK;
        const float2* szpN = szbase + (size_t)gN * N_OUT + nbN;

        // ---- dequant chunk w -> Bs[p], interleaving next-chunk LDG refill ----
        __half* Bsb = Bs + p * (BN * LDK);
        #pragma unroll
        for (int it = 0; it < 8; ++it) {
            const int4     q   = wq[it];
            const uint32_t szv = szr[it];
            wq[it] = *reinterpret_cast<const int4*>(qrN + (size_t)(it * 8) * K_IN);
            {
                float2 v = szpN[it * 8];
                __half2 h = __floats2half2_rn(v.x, v.y);
                szr[it] = *reinterpret_cast<uint32_t*>(&h);
            }
            const int nloc = it * 8 + warp;
            const __half2 szh = *reinterpret_cast<const __half2*>(&szv);
            const __half2 s2 = __half2half2(__low2half(szh));
            const __half2 z2 = __half2half2(__high2half(szh));
            uint32_t p0 = 0x64006400u | (uint32_t)q.x | ((uint32_t)q.y << 16);
            uint32_t p1 = 0x64006400u | (uint32_t)q.z | ((uint32_t)q.w << 16);
            __half2 h0 = __hsub2(*reinterpret_cast<const __half2*>(&p0), k1032);
            __half2 h1 = __hsub2(*reinterpret_cast<const __half2*>(&p1), k1032);
            __half2 w0h = __hfma2(h0, s2, z2);
            __half2 w1h = __hfma2(h1, s2, z2);
            uint2 pk;
            pk.x = *reinterpret_cast<uint32_t*>(&w0h);
            pk.y = *reinterpret_cast<uint32_t*>(&w1h);
            *reinterpret_cast<uint2*>(&Bsb[nloc * LDK + lane * 4]) = pk;
        }
        __syncthreads();   // publishes Bs[p] and As[p]; MMA(w-1) done -> As[p^1] free

        // ---- stage x(w+1) into the freed As buffer ----
        if (w + 1 < w1)
            stage_x(gN, p ^ 1);

        // ---- MMA ----
        const uint32_t ab  = a_off  + p * ABYTES;
        const uint32_t bb0 = b_off0 + p * BBYTES;
        const uint32_t bb1 = b_off1 + p * BBYTES;
        #pragma unroll
        for (int kk = 0; kk < 8; ++kk) {
            uint32_t a0, a1, a2, a3;
            ldsm4(a0, a1, a2, a3, ab + kk * 32);
            uint32_t b0, b1, b2, b3, b4, b5, b6, b7;
            ldsm4(b0, b1, b2, b3, bb0 + kk * 32);
            ldsm4(b4, b5, b6, b7, bb1 + kk * 32);
            mma_16816(acc[0], a0, a1, a2, a3, b0, b1);
            mma_16816(acc[1], a0, a1, a2, a3, b2, b3);
            mma_16816(acc[2], a0, a1, a2, a3, b4, b5);
            mma_16816(acc[3], a0, a1, a2, a3, b6, b7);
        }

        // ---- segment boundary: write partial 64x64 block ----
        if (w + 1 == w1 || ((w + 1) >> 6) != (w >> 6)) {
            float* part = g_part + ((size_t)cta * 2 + seg) * 4096;
            const int row = wm * 16 + (lane >> 2);
            #pragma unroll
            for (int j = 0; j < 4; ++j) {
                const int col = wn * 32 + j * 8 + (lane & 3) * 2;
                *reinterpret_cast<float2*>(part + row * 64 + col) =
                    make_float2(acc[j][0], acc[j][1]);
                *reinterpret_cast<float2*>(part + (row + 8) * 64 + col) =
                    make_float2(acc[j][2], acc[j][3]);
                acc[j][0] = acc[j][1] = acc[j][2] = acc[j][3] = 0.f;
            }
            ++seg;
        }
    }

    // ================= epilogue: last-arriver reduces its ntile(s) =================
    __shared__ int s_red[2];
    __threadfence();        // make this CTA's partials device-visible
    __syncthreads();        // all threads' stores+fences ordered before tid0's atomics
    if (tid == 0) {
        s_red[0] = -1; s_red[1] = -1;
        const int ntA = w0 >> 6;
        const int ntB = (w1 - 1) >> 6;
        #pragma unroll
        for (int k = 0; k < 2; ++k) {
            if (k && ntB == ntA) break;
            const int nt = k ? ntB : ntA;
            const int X = nt << 6;
            int c0 = (int)(((long long)X * NCTA) >> 13);
            while (gsplit(c0 + 1) <= X) ++c0;
            int cnt = 0;
            while (c0 + cnt < NCTA && gsplit(c0 + cnt) < X + 64) ++cnt;
            const int old = atomicAdd(&g_cnt[nt], 1);
            if (old == cnt - 1) s_red[k] = nt;
        }
    }
    __syncthreads();
    #pragma unroll
    for (int k = 0; k < 2; ++k) {
        const int nt = s_red[k];
        if (nt < 0) continue;
        __threadfence();    // acquire: contributors' partials visible to all threads
        const int X = nt << 6;
        int c0 = (int)(((long long)X * NCTA) >> 13);
        while (gsplit(c0 + 1) <= X) ++c0;
        int cnt = 0;
        while (c0 + cnt < NCTA && gsplit(c0 + cnt) < X + 64) ++cnt;
        for (int idx = tid; idx < 4096; idx += NTHREADS) {
            const int m = idx >> 6, nl = idx & 63;
            float s = 0.f;
            for (int j = 0; j < cnt; ++j) {
                const int c = c0 + j;
                const int sg = ((gsplit(c) >> 6) == nt) ? 0 : 1;
                s += __ldcg(g_part + ((size_t)c * 2 + sg) * 4096 + m * 64 + nl);
            }
            out[(size_t)m * N_OUT + X + nl] = s;
        }
        if (tid == 0) atomicExch(&g_cnt[nt], 0);   // reset for next graph replay
    }
}

extern "C" void kernel_launch(void* const* d_in, const int* in_sizes, int n_in,
                              void* d_out, int out_size) {
    const float* x  = (const float*)d_in[0];   // (64, 8192) fp32
    const int*   qw = (const int*)d_in[1];     // (8192, 8192) int32 in [0,15]
    const float* sz = (const float*)d_in[2];   // (64, 8192, 2) fp32
    float* out = (float*)d_out;                // (64, 8192) fp32

    static bool attr_set = false;
    if (!attr_set) {
        cudaFuncSetAttribute(woq_gemm_kernel,
                             cudaFuncAttributeMaxDynamicSharedMemorySize, SMEM_BYTES);
        attr_set = true;
    }
    woq_gemm_kernel<<<NCTA, NTHREADS, SMEM_BYTES>>>(x, qw, sz, out);
}

// round 16
// speedup vs baseline: 1.1595x; 1.1595x over previous
#include <cuda_runtime.h>
#include <cuda_fp16.h>
#include <cstdint>

#define M_TOK 64
#define N_OUT 8192
#define K_IN  8192
#define NG    64            // K groups per row (8192/128)
#define NTILES (N_OUT / 64) // 128
#define WTOTAL (NTILES * NG)// 8192 work units
#define NCTA  296           // 2 per SM on 148 SMs
#define BN    64
#define BK    128
#define LDK   136
#define NTHREADS 256
#define ABYTES (M_TOK * LDK * 2)
#define BBYTES (BN * LDK * 2)
#define SMEM_BYTES (2 * ABYTES + 2 * BBYTES)  // 69632 B -> 2 CTA/SM

__device__ __half   g_xh[M_TOK * K_IN];      // x in fp16 (1 MB)
__device__ uint32_t g_szp[NG * N_OUT];       // packed (s,z) half2 (2 MB)
__device__ float    g_part[NCTA * 2 * 4096]; // stream-K partials
__device__ int      g_cnt[NTILES];           // per-ntile arrival counters (self-resetting)

__device__ __forceinline__ int gsplit(int c) { return (int)(((long long)c * WTOTAL) / NCTA); }

// ---- prep: convert x to fp16 + pack (s,z) to half2; 16 floats/thread ----
__global__ void prep_kernel(const float* __restrict__ x, const float* __restrict__ sz) {
    const int NX = M_TOK * K_IN / 16;
    int t = blockIdx.x * blockDim.x + threadIdx.x;
    const float* src = (t < NX) ? (x + (size_t)t * 16) : (sz + (size_t)(t - NX) * 16);
    uint32_t* dst = (t < NX) ? reinterpret_cast<uint32_t*>(g_xh + (size_t)t * 16)
                             : (g_szp + (size_t)(t - NX) * 8);
    float4 v0 = *reinterpret_cast<const float4*>(src);
    float4 v1 = *reinterpret_cast<const float4*>(src + 4);
    float4 v2 = *reinterpret_cast<const float4*>(src + 8);
    float4 v3 = *reinterpret_cast<const float4*>(src + 12);
    __half2 h0 = __floats2half2_rn(v0.x, v0.y);
    __half2 h1 = __floats2half2_rn(v0.z, v0.w);
    __half2 h2 = __floats2half2_rn(v1.x, v1.y);
    __half2 h3 = __floats2half2_rn(v1.z, v1.w);
    __half2 h4 = __floats2half2_rn(v2.x, v2.y);
    __half2 h5 = __floats2half2_rn(v2.z, v2.w);
    __half2 h6 = __floats2half2_rn(v3.x, v3.y);
    __half2 h7 = __floats2half2_rn(v3.z, v3.w);
    uint4 pa, pb;
    pa.x = *reinterpret_cast<uint32_t*>(&h0);
    pa.y = *reinterpret_cast<uint32_t*>(&h1);
    pa.z = *reinterpret_cast<uint32_t*>(&h2);
    pa.w = *reinterpret_cast<uint32_t*>(&h3);
    pb.x = *reinterpret_cast<uint32_t*>(&h4);
    pb.y = *reinterpret_cast<uint32_t*>(&h5);
    pb.z = *reinterpret_cast<uint32_t*>(&h6);
    pb.w = *reinterpret_cast<uint32_t*>(&h7);
    *reinterpret_cast<uint4*>(dst)     = pa;
    *reinterpret_cast<uint4*>(dst + 4) = pb;
}

__device__ __forceinline__ void cp16(uint32_t dst, const void* src) {
    asm volatile("cp.async.cg.shared.global [%0], [%1], 16;" :: "r"(dst), "l"(src));
}
__device__ __forceinline__ void ldsm4(uint32_t& r0, uint32_t& r1, uint32_t& r2, uint32_t& r3,
                                      uint32_t a) {
    asm volatile("ldmatrix.sync.aligned.m8n8.x4.shared.b16 {%0,%1,%2,%3}, [%4];"
                 : "=r"(r0), "=r"(r1), "=r"(r2), "=r"(r3) : "r"(a));
}
__device__ __forceinline__ void mma_16816(float c[4],
                                          uint32_t a0, uint32_t a1, uint32_t a2, uint32_t a3,
                                          uint32_t b0, uint32_t b1) {
    asm volatile("mma.sync.aligned.m16n8k16.row.col.f32.f16.f16.f32 "
                 "{%0,%1,%2,%3}, {%4,%5,%6,%7}, {%8,%9}, {%0,%1,%2,%3};"
                 : "+f"(c[0]), "+f"(c[1]), "+f"(c[2]), "+f"(c[3])
                 : "r"(a0), "r"(a1), "r"(a2), "r"(a3), "r"(b0), "r"(b1));
}

__global__ void __launch_bounds__(NTHREADS, 2)
woq_gemm_kernel(const int* __restrict__ qw, float* __restrict__ out)
{
    extern __shared__ __half smem[];
    __half* Bs = smem + 2 * M_TOK * LDK;

    const int tid  = threadIdx.x;
    const int lane = tid & 31;
    const int warp = tid >> 5;
    const int wm   = warp & 3;
    const int wn   = warp >> 2;
    const int cta  = blockIdx.x;

    const int w0 = gsplit(cta);
    const int w1 = gsplit(cta + 1);

    float acc[4][4];
    #pragma unroll
    for (int i = 0; i < 4; ++i)
        #pragma unroll
        for (int j = 0; j < 4; ++j) acc[i][j] = 0.f;

    const uint32_t s_base = (uint32_t)__cvta_generic_to_shared(smem);
    const uint32_t as_b = s_base;
    const uint32_t bs_b = s_base + 2 * ABYTES;

    const uint32_t a_off  = as_b + 2u * ((wm * 16 + (lane & 15)) * LDK + (lane >> 4) * 8);
    const uint32_t b_off0 = bs_b + 2u * ((wn * 32 + (lane & 7) + ((lane >> 4) << 3)) * LDK
                                         + ((lane >> 3) & 1) * 8);
    const uint32_t b_off1 = b_off0 + 2u * 16 * LDK;

    const int xrow0 = tid >> 4;
    const int xcol  = tid & 15;
    const __half* xsrc = g_xh + (size_t)xrow0 * K_IN + xcol * 8;
    const uint32_t adst = as_b + 2u * (xrow0 * LDK + xcol * 8);

    int4     wq[8];    // staged weights for CURRENT chunk
    uint32_t szr[8];   // staged packed (s,z) for CURRENT chunk

    const int*      qbase  = qw + (size_t)warp * K_IN + lane * 4;
    const uint32_t* szbase = g_szp + warp;

    // ---- prologue: fill regs for chunk w0, start As(w0) ----
    {
        const int g  = w0 & (NG - 1);
        const int nb = (w0 >> 6) << 6;
        const int k0 = g * BK;
        #pragma unroll
        for (int j = 0; j < 4; ++j)
            cp16(adst + j * (16 * LDK * 2), xsrc + (size_t)j * 16 * K_IN + k0);
        asm volatile("cp.async.commit_group;");
        const int* qr = qbase + (size_t)nb * K_IN + k0;
        #pragma unroll
        for (int it = 0; it < 8; ++it)
            wq[it] = *reinterpret_cast<const int4*>(qr + (size_t)(it * 8) * K_IN);
        const uint32_t* szp = szbase + (size_t)g * N_OUT + nb;
        #pragma unroll
        for (int it = 0; it < 8; ++it)
            szr[it] = szp[it * 8];
    }

    const __half2 k1032 = __floats2half2_rn(1032.f, 1032.f);
    int seg = 0;

    for (int w = w0; w < w1; ++w) {
        const int p = (w - w0) & 1;

        const int wn_ = (w + 1 < w1) ? (w + 1) : w;
        const int gN  = wn_ & (NG - 1);
        const int nbN = (wn_ >> 6) << 6;
        const int* qrN = qbase + (size_t)nbN * K_IN + gN * BK;
        const uint32_t* szpN = szbase + (size_t)gN * N_OUT + nbN;

        asm volatile("cp.async.wait_group 0;");

        // ---- dequant chunk w -> Bs[p], interleaving next-chunk LDG refill ----
        __half* Bsb = Bs + p * (BN * LDK);
        #pragma unroll
        for (int it = 0; it < 8; ++it) {
            const int4     q   = wq[it];
            const uint32_t szv = szr[it];
            wq[it]  = *reinterpret_cast<const int4*>(qrN + (size_t)(it * 8) * K_IN);
            szr[it] = szpN[it * 8];
            const int nloc = it * 8 + warp;
            const __half2 szh = *reinterpret_cast<const __half2*>(&szv);
            const __half2 s2 = __half2half2(__low2half(szh));
            const __half2 z2 = __half2half2(__high2half(szh));
            uint32_t p0 = 0x64006400u | (uint32_t)q.x | ((uint32_t)q.y << 16);
            uint32_t p1 = 0x64006400u | (uint32_t)q.z | ((uint32_t)q.w << 16);
            __half2 h0 = __hsub2(*reinterpret_cast<const __half2*>(&p0), k1032);
            __half2 h1 = __hsub2(*reinterpret_cast<const __half2*>(&p1), k1032);
            __half2 w0h = __hfma2(h0, s2, z2);
            __half2 w1h = __hfma2(h1, s2, z2);
            uint2 pk;
            pk.x = *reinterpret_cast<uint32_t*>(&w0h);
            pk.y = *reinterpret_cast<uint32_t*>(&w1h);
            *reinterpret_cast<uint2*>(&Bsb[nloc * LDK + lane * 4]) = pk;
        }
        __syncthreads();   // Bs[p] published; all warps done with MMA(w-1)

        // ---- issue As(w+1) into the freed buffer ----
        if (w + 1 < w1) {
            const int k0N = gN * BK;
            #pragma unroll
            for (int j = 0; j < 4; ++j)
                cp16(adst + (p ^ 1) * ABYTES + j * (16 * LDK * 2),
                     xsrc + (size_t)j * 16 * K_IN + k0N);
        }
        asm volatile("cp.async.commit_group;");

        // ---- MMA ----
        const uint32_t ab  = a_off  + p * ABYTES;
        const uint32_t bb0 = b_off0 + p * BBYTES;
        const uint32_t bb1 = b_off1 + p * BBYTES;
        #pragma unroll
        for (int kk = 0; kk < 8; ++kk) {
            uint32_t a0, a1, a2, a3;
            ldsm4(a0, a1, a2, a3, ab + kk * 32);
            uint32_t b0, b1, b2, b3, b4, b5, b6, b7;
            ldsm4(b0, b1, b2, b3, bb0 + kk * 32);
            ldsm4(b4, b5, b6, b7, bb1 + kk * 32);
            mma_16816(acc[0], a0, a1, a2, a3, b0, b1);
            mma_16816(acc[1], a0, a1, a2, a3, b2, b3);
            mma_16816(acc[2], a0, a1, a2, a3, b4, b5);
            mma_16816(acc[3], a0, a1, a2, a3, b6, b7);
        }

        // ---- segment boundary: write partial 64x64 block ----
        if (w + 1 == w1 || ((w + 1) >> 6) != (w >> 6)) {
            float* part = g_part + ((size_t)cta * 2 + seg) * 4096;
            const int row = wm * 16 + (lane >> 2);
            #pragma unroll
            for (int j = 0; j < 4; ++j) {
                const int col = wn * 32 + j * 8 + (lane & 3) * 2;
                *reinterpret_cast<float2*>(part + row * 64 + col) =
                    make_float2(acc[j][0], acc[j][1]);
                *reinterpret_cast<float2*>(part + (row + 8) * 64 + col) =
                    make_float2(acc[j][2], acc[j][3]);
                acc[j][0] = acc[j][1] = acc[j][2] = acc[j][3] = 0.f;
            }
            ++seg;
        }
    }

    // ======== epilogue: last-arriving CTA per ntile reduces it to out ========
    __shared__ int s_red[2];
    __threadfence();        // release this CTA's partial stores
    __syncthreads();        // order all threads' stores before tid0's atomics
    if (tid == 0) {
        s_red[0] = -1; s_red[1] = -1;
        const int ntA = w0 >> 6;
        const int ntB = (w1 - 1) >> 6;
        #pragma unroll
        for (int k = 0; k < 2; ++k) {
            if (k && ntB == ntA) break;
            const int nt = k ? ntB : ntA;
            const int X = nt << 6;
            int c0 = (int)(((long long)X * NCTA) >> 13);
            while (gsplit(c0 + 1) <= X) ++c0;
            int cnt = 0;
            while (c0 + cnt < NCTA && gsplit(c0 + cnt) < X + 64) ++cnt;
            const int old = atomicAdd(&g_cnt[nt], 1);
            if (old == cnt - 1) s_red[k] = nt;
        }
    }
    __syncthreads();
    #pragma unroll
    for (int k = 0; k < 2; ++k) {
        const int nt = s_red[k];
        if (nt < 0) continue;
        __threadfence();    // acquire: contributors' partials visible
        const int X = nt << 6;
        int c0 = (int)(((long long)X * NCTA) >> 13);
        while (gsplit(c0 + 1) <= X) ++c0;
        int cnt = 0;
        while (c0 + cnt < NCTA && gsplit(c0 + cnt) < X + 64) ++cnt;
        for (int idx = tid; idx < 4096; idx += NTHREADS) {
            const int m = idx >> 6, nl = idx & 63;
            float s = 0.f;
            for (int j = 0; j < cnt; ++j) {
                const int c = c0 + j;
                const int sg = ((gsplit(c) >> 6) == nt) ? 0 : 1;
                s += __ldcg(g_part + ((size_t)c * 2 + sg) * 4096 + m * 64 + nl);
            }
            out[(size_t)m * N_OUT + X + nl] = s;
        }
        if (tid == 0) atomicExch(&g_cnt[nt], 0);   // reset for next graph replay
    }
}

extern "C" void kernel_launch(void* const* d_in, const int* in_sizes, int n_in,
                              void* d_out, int out_size) {
    const float* x  = (const float*)d_in[0];   // (64, 8192) fp32
    const int*   qw = (const int*)d_in[1];     // (8192, 8192) int32 in [0,15]
    const float* sz = (const float*)d_in[2];   // (64, 8192, 2) fp32
    float* out = (float*)d_out;                // (64, 8192) fp32

    static bool attr_set = false;
    if (!attr_set) {
        cudaFuncSetAttribute(woq_gemm_kernel,
                             cudaFuncAttributeMaxDynamicSharedMemorySize, SMEM_BYTES);
        attr_set = true;
    }

    const int n_prep = (M_TOK * K_IN / 16) + (NG * N_OUT / 8);  // 98304 threads
    prep_kernel<<<n_prep / 256, 256>>>(x, sz);
    woq_gemm_kernel<<<NCTA, NTHREADS, SMEM_BYTES>>>(qw, out);
}

// round 17
// speedup vs baseline: 1.6414x; 1.4156x over previous
#include <cuda_runtime.h>
#include <cuda_fp16.h>
#include <cstdint>

#define M_TOK 64
#define N_OUT 8192
#define K_IN  8192
#define NG    64            // K groups per row (8192/128)
#define NTILES (N_OUT / 64) // 128
#define WTOTAL (NTILES * NG)// 8192 work units
#define NCTA  296           // 2 per SM on 148 SMs, all resident
#define BN    64
#define BK    128
#define LDK   136
#define NTHREADS 256
#define ABYTES (M_TOK * LDK * 2)
#define BBYTES (BN * LDK * 2)
#define SMEM_BYTES (2 * ABYTES + 2 * BBYTES)  // 69632 B -> 2 CTA/SM

__device__ __half   g_xh[M_TOK * K_IN];      // x in fp16 (1 MB)
__device__ uint32_t g_szp[NG * N_OUT];       // packed (s,z) half2 (2 MB)
__device__ float    g_part[NCTA * 2 * 4096]; // stream-K partials

__device__ __forceinline__ int gsplit(int c) { return (int)(((long long)c * WTOTAL) / NCTA); }

// ---- prep: convert x to fp16 + pack (s,z) to half2; 16 floats/thread ----
__global__ void prep_kernel(const float* __restrict__ x, const float* __restrict__ sz) {
    const int NX = M_TOK * K_IN / 16;   // 32768 threads for x
    int t = blockIdx.x * blockDim.x + threadIdx.x;
    const float* src = (t < NX) ? (x + (size_t)t * 16)
                                : (sz + (size_t)(t - NX) * 16);
    uint32_t* dst = (t < NX) ? reinterpret_cast<uint32_t*>(g_xh + (size_t)t * 16)
                             : (g_szp + (size_t)(t - NX) * 8);
    float4 v0 = *reinterpret_cast<const float4*>(src);
    float4 v1 = *reinterpret_cast<const float4*>(src + 4);
    float4 v2 = *reinterpret_cast<const float4*>(src + 8);
    float4 v3 = *reinterpret_cast<const float4*>(src + 12);
    __half2 h0 = __floats2half2_rn(v0.x, v0.y);
    __half2 h1 = __floats2half2_rn(v0.z, v0.w);
    __half2 h2 = __floats2half2_rn(v1.x, v1.y);
    __half2 h3 = __floats2half2_rn(v1.z, v1.w);
    __half2 h4 = __floats2half2_rn(v2.x, v2.y);
    __half2 h5 = __floats2half2_rn(v2.z, v2.w);
    __half2 h6 = __floats2half2_rn(v3.x, v3.y);
    __half2 h7 = __floats2half2_rn(v3.z, v3.w);
    uint4 pa, pb;
    pa.x = *reinterpret_cast<uint32_t*>(&h0);
    pa.y = *reinterpret_cast<uint32_t*>(&h1);
    pa.z = *reinterpret_cast<uint32_t*>(&h2);
    pa.w = *reinterpret_cast<uint32_t*>(&h3);
    pb.x = *reinterpret_cast<uint32_t*>(&h4);
    pb.y = *reinterpret_cast<uint32_t*>(&h5);
    pb.z = *reinterpret_cast<uint32_t*>(&h6);
    pb.w = *reinterpret_cast<uint32_t*>(&h7);
    *reinterpret_cast<uint4*>(dst)     = pa;
    *reinterpret_cast<uint4*>(dst + 4) = pb;
}

// ---- stream-K reduce: 4 floats/thread, float4 path ----
__global__ void reduce_kernel(float* __restrict__ out) {
    int i4 = (blockIdx.x * blockDim.x + threadIdx.x) * 4;
    int m  = i4 >> 13;
    int n  = i4 & (N_OUT - 1);
    int nt = n >> 6, nl = n & 63;        // nl is 4-aligned
    int X  = nt << 6;
    int c  = (int)(((long long)X * NCTA) >> 13);
    while (gsplit(c + 1) <= X) ++c;
    float4 s = make_float4(0.f, 0.f, 0.f, 0.f);
    while (c < NCTA && gsplit(c) < X + 64) {
        int seg = ((gsplit(c) >> 6) == nt) ? 0 : 1;
        const float4 v = *reinterpret_cast<const float4*>(
            g_part + ((size_t)c * 2 + seg) * 4096 + m * 64 + nl);
        s.x += v.x; s.y += v.y; s.z += v.z; s.w += v.w;
        ++c;
    }
    *reinterpret_cast<float4*>(out + i4) = s;
}

__device__ __forceinline__ void cp16(uint32_t dst, const void* src) {
    asm volatile("cp.async.cg.shared.global [%0], [%1], 16;" :: "r"(dst), "l"(src));
}
__device__ __forceinline__ void ldsm4(uint32_t& r0, uint32_t& r1, uint32_t& r2, uint32_t& r3,
                                      uint32_t a) {
    asm volatile("ldmatrix.sync.aligned.m8n8.x4.shared.b16 {%0,%1,%2,%3}, [%4];"
                 : "=r"(r0), "=r"(r1), "=r"(r2), "=r"(r3) : "r"(a));
}
__device__ __forceinline__ void mma_16816(float c[4],
                                          uint32_t a0, uint32_t a1, uint32_t a2, uint32_t a3,
                                          uint32_t b0, uint32_t b1) {
    asm volatile("mma.sync.aligned.m16n8k16.row.col.f32.f16.f16.f32 "
                 "{%0,%1,%2,%3}, {%4,%5,%6,%7}, {%8,%9}, {%0,%1,%2,%3};"
                 : "+f"(c[0]), "+f"(c[1]), "+f"(c[2]), "+f"(c[3])
                 : "r"(a0), "r"(a1), "r"(a2), "r"(a3), "r"(b0), "r"(b1));
}

__global__ void __launch_bounds__(NTHREADS, 2)
woq_gemm_kernel(const int* __restrict__ qw)
{
    extern __shared__ __half smem[];
    __half* Bs = smem + 2 * M_TOK * LDK;

    const int tid  = threadIdx.x;
    const int lane = tid & 31;
    const int warp = tid >> 5;
    const int wm   = warp & 3;
    const int wn   = warp >> 2;
    const int cta  = blockIdx.x;

    const int w0 = gsplit(cta);
    const int w1 = gsplit(cta + 1);

    float acc[4][4];
    #pragma unroll
    for (int i = 0; i < 4; ++i)
        #pragma unroll
        for (int j = 0; j < 4; ++j) acc[i][j] = 0.f;

    const uint32_t s_base = (uint32_t)__cvta_generic_to_shared(smem);
    const uint32_t as_b = s_base;
    const uint32_t bs_b = s_base + 2 * ABYTES;

    const uint32_t a_off  = as_b + 2u * ((wm * 16 + (lane & 15)) * LDK + (lane >> 4) * 8);
    const uint32_t b_off0 = bs_b + 2u * ((wn * 32 + (lane & 7) + ((lane >> 4) << 3)) * LDK
                                         + ((lane >> 3) & 1) * 8);
    const uint32_t b_off1 = b_off0 + 2u * 16 * LDK;

    const int xrow0 = tid >> 4;
    const int xcol  = tid & 15;
    const __half* xsrc = g_xh + (size_t)xrow0 * K_IN + xcol * 8;
    const uint32_t adst = as_b + 2u * (xrow0 * LDK + xcol * 8);

    int4     wq[8];    // staged weights for the CURRENT chunk
    uint32_t szr[8];   // staged packed (s,z) for the CURRENT chunk

    // per-thread fixed offsets
    const int*      qbase  = qw + (size_t)warp * K_IN + lane * 4;
    const uint32_t* szbase = g_szp + warp;

    // ---- prologue: fill regs for chunk w0, start As(w0) ----
    {
        const int g  = w0 & (NG - 1);
        const int nb = (w0 >> 6) << 6;
        const int k0 = g * BK;
        #pragma unroll
        for (int j = 0; j < 4; ++j)
            cp16(adst + j * (16 * LDK * 2), xsrc + (size_t)j * 16 * K_IN + k0);
        asm volatile("cp.async.commit_group;");
        const int* qr = qbase + (size_t)nb * K_IN + k0;
        #pragma unroll
        for (int it = 0; it < 8; ++it)
            wq[it] = *reinterpret_cast<const int4*>(qr + (size_t)(it * 8) * K_IN);
        const uint32_t* szp = szbase + (size_t)g * N_OUT + nb;
        #pragma unroll
        for (int it = 0; it < 8; ++it)
            szr[it] = szp[it * 8];
    }

    const __half2 k1032 = __floats2half2_rn(1032.f, 1032.f);
    int seg = 0;

    for (int w = w0; w < w1; ++w) {
        const int p = (w - w0) & 1;

        // next-chunk addresses (clamped to w on the last chunk: harmless reload)
        const int wn_ = (w + 1 < w1) ? (w + 1) : w;
        const int gN  = wn_ & (NG - 1);
        const int nbN = (wn_ >> 6) << 6;
        const int* qrN = qbase + (size_t)nbN * K_IN + gN * BK;
        const uint32_t* szpN = szbase + (size_t)gN * N_OUT + nbN;

        asm volatile("cp.async.wait_group 0;");

        // ---- dequant chunk w -> Bs[p], interleaving next-chunk LDG issue.
        // wq[it]/szr[it] are consumed at iteration it and refilled immediately:
        // the w+1 DRAM loads get dequant-rest + barrier + MMA + barrier of cover.
        __half* Bsb = Bs + p * (BN * LDK);
        #pragma unroll
        for (int it = 0; it < 8; ++it) {
            const int4     q   = wq[it];
            const uint32_t szv = szr[it];
            wq[it]  = *reinterpret_cast<const int4*>(qrN + (size_t)(it * 8) * K_IN);
            szr[it] = szpN[it * 8];
            const int nloc = it * 8 + warp;
            const __half2 szh = *reinterpret_cast<const __half2*>(&szv);
            const __half2 s2 = __half2half2(__low2half(szh));
            const __half2 z2 = __half2half2(__high2half(szh));
            uint32_t p0 = 0x64006400u | (uint32_t)q.x | ((uint32_t)q.y << 16);
            uint32_t p1 = 0x64006400u | (uint32_t)q.z | ((uint32_t)q.w << 16);
            __half2 h0 = __hsub2(*reinterpret_cast<const __half2*>(&p0), k1032);
            __half2 h1 = __hsub2(*reinterpret_cast<const __half2*>(&p1), k1032);
            __half2 w0h = __hfma2(h0, s2, z2);
            __half2 w1h = __hfma2(h1, s2, z2);
            uint2 pk;
            pk.x = *reinterpret_cast<uint32_t*>(&w0h);
            pk.y = *reinterpret_cast<uint32_t*>(&w1h);
            *reinterpret_cast<uint2*>(&Bsb[nloc * LDK + lane * 4]) = pk;
        }
        __syncthreads();   // Bs[p] published; all warps done with MMA(w-1)

        // ---- issue As(w+1) into the freed buffer ----
        if (w + 1 < w1) {
            const int k0N = gN * BK;
            #pragma unroll
            for (int j = 0; j < 4; ++j)
                cp16(adst + (p ^ 1) * ABYTES + j * (16 * LDK * 2),
                     xsrc + (size_t)j * 16 * K_IN + k0N);
        }
        asm volatile("cp.async.commit_group;");

        // ---- MMA ----
        const uint32_t ab  = a_off  + p * ABYTES;
        const uint32_t bb0 = b_off0 + p * BBYTES;
        const uint32_t bb1 = b_off1 + p * BBYTES;
        #pragma unroll
        for (int kk = 0; kk < 8; ++kk) {
            uint32_t a0, a1, a2, a3;
            ldsm4(a0, a1, a2, a3, ab + kk * 32);
            uint32_t b0, b1, b2, b3, b4, b5, b6, b7;
            ldsm4(b0, b1, b2, b3, bb0 + kk * 32);
            ldsm4(b4, b5, b6, b7, bb1 + kk * 32);
            mma_16816(acc[0], a0, a1, a2, a3, b0, b1);
            mma_16816(acc[1], a0, a1, a2, a3, b2, b3);
            mma_16816(acc[2], a0, a1, a2, a3, b4, b5);
            mma_16816(acc[3], a0, a1, a2, a3, b6, b7);
        }

        // ---- segment boundary: write partial 64x64 block ----
        if (w + 1 == w1 || ((w + 1) >> 6) != (w >> 6)) {
            float* part = g_part + ((size_t)cta * 2 + seg) * 4096;
            const int row = wm * 16 + (lane >> 2);
            #pragma unroll
            for (int j = 0; j < 4; ++j) {
                const int col = wn * 32 + j * 8 + (lane & 3) * 2;
                *reinterpret_cast<float2*>(part + row * 64 + col) =
                    make_float2(acc[j][0], acc[j][1]);
                *reinterpret_cast<float2*>(part + (row + 8) * 64 + col) =
                    make_float2(acc[j][2], acc[j][3]);
                acc[j][0] = acc[j][1] = acc[j][2] = acc[j][3] = 0.f;
            }
            ++seg;
        }
    }
}

extern "C" void kernel_launch(void* const* d_in, const int* in_sizes, int n_in,
                              void* d_out, int out_size) {
    const float* x  = (const float*)d_in[0];   // (64, 8192) fp32
    const int*   qw = (const int*)d_in[1];     // (8192, 8192) int32 in [0,15]
    const float* sz = (const float*)d_in[2];   // (64, 8192, 2) fp32
    float* out = (float*)d_out;                // (64, 8192) fp32

    static bool attr_set = false;
    if (!attr_set) {
        cudaFuncSetAttribute(woq_gemm_kernel,
                             cudaFuncAttributeMaxDynamicSharedMemorySize, SMEM_BYTES);
        attr_set = true;
    }

    const int n_prep = (M_TOK * K_IN / 16) + (NG * N_OUT / 8);  // 98304 threads
    prep_kernel<<<n_prep / 256, 256>>>(x, sz);
    woq_gemm_kernel<<<NCTA, NTHREADS, SMEM_BYTES>>>(qw);
    reduce_kernel<<<(M_TOK * N_OUT / 4) / 256, 256>>>(out);
}